// round 9
// baseline (speedup 1.0000x reference)
#include <cuda_runtime.h>
#include <cstdint>
#include <math.h>

#define BB 4
#define TT 1024
#define DMODEL 512
#define HH 8
#define NEG_INF_F (-1000000000.0f)
#define NROWS (HH*BB*TT)   // 32768 softmax rows
#define NSTAT 16           // per-row stat slots (64-col granularity)

// ---------------- scratch (device globals; no allocation) ----------------
__device__ float g_q[BB*TT*DMODEL];
__device__ float g_k[BB*TT*DMODEL];
__device__ float g_v[BB*TT*DMODEL];
__device__ float g_res[BB*TT*DMODEL];
__device__ float g_scores[(size_t)HH*BB*TT*TT];   // 134 MB
__device__ float g_smax[(size_t)NROWS*NSTAT];
__device__ float g_ssum[(size_t)NROWS*NSTAT];
__device__ float g_mrow[NROWS];
__device__ float g_linv[NROWS];
__device__ float g_maskv[HH*DMODEL];
__device__ float g_m2[HH*DMODEL];
__device__ float g_inv_scale[HH];
__device__ int   g_dlo[HH];
__device__ int   g_dhi[HH];
__device__ float g_ctx[BB*TT*DMODEL];

// ================= mma.sync tf32 machinery =================
__device__ __forceinline__ float tf32_rna(float x) {
    float r; asm("cvt.rna.tf32.f32 %0, %1;" : "=f"(r) : "f"(x)); return r;
}
__device__ __forceinline__ float2 split_tf32(float x) {
    float h = tf32_rna(x);
    float l = tf32_rna(x - h);
    return make_float2(h, l);
}
__device__ __forceinline__ void mma8(float c[4], const uint32_t a[4], uint32_t b0, uint32_t b1) {
    asm volatile(
        "mma.sync.aligned.m16n8k8.row.col.f32.tf32.tf32.f32 "
        "{%0,%1,%2,%3}, {%4,%5,%6,%7}, {%8,%9}, {%0,%1,%2,%3};"
        : "+f"(c[0]), "+f"(c[1]), "+f"(c[2]), "+f"(c[3])
        : "r"(a[0]), "r"(a[1]), "r"(a[2]), "r"(a[3]), "r"(b0), "r"(b1));
}

#define PAD 133   // float2 per k-row

// A fill: src row-major [m][k] (ld), tile rows m0..m0+127, cols k0..k0+15 -> As[k][m]
__device__ __forceinline__ void fillA_plain(const float* __restrict__ src, int ld, int m0, int k0,
                                            float2 (*As)[PAD], int tid) {
    #pragma unroll
    for (int it = 0; it < 2; it++) {
        int idx = it*256 + tid;
        int m = idx >> 2, k4 = (idx & 3) << 2;
        float4 v = *(const float4*)(src + (size_t)(m0+m)*ld + k0 + k4);
        As[k4+0][m] = split_tf32(v.x);
        As[k4+1][m] = split_tf32(v.y);
        As[k4+2][m] = split_tf32(v.z);
        As[k4+3][m] = split_tf32(v.w);
    }
}
// A fill with per-k scale (Q * m2) for scores
__device__ __forceinline__ void fillA_scaled(const float* __restrict__ src, int ld, int m0, int k0,
                                             const float* __restrict__ scl,
                                             float2 (*As)[PAD], int tid) {
    #pragma unroll
    for (int it = 0; it < 2; it++) {
        int idx = it*256 + tid;
        int m = idx >> 2, k4 = (idx & 3) << 2;
        float4 v = *(const float4*)(src + (size_t)(m0+m)*ld + k0 + k4);
        float4 s = *(const float4*)(scl + k0 + k4);
        As[k4+0][m] = split_tf32(v.x * s.x);
        As[k4+1][m] = split_tf32(v.y * s.y);
        As[k4+2][m] = split_tf32(v.z * s.z);
        As[k4+3][m] = split_tf32(v.w * s.w);
    }
}
// B fill along n: src row-major [k][n] (ld) -> Bs[k][n]
__device__ __forceinline__ void fillB_n(const float* __restrict__ src, int ld, int k0, int n0,
                                        float2 (*Bs)[PAD], int tid) {
    #pragma unroll
    for (int it = 0; it < 2; it++) {
        int idx = it*256 + tid;
        int k = idx >> 5, n4 = (idx & 31) << 2;
        float4 v = *(const float4*)(src + (size_t)(k0+k)*ld + n0 + n4);
        Bs[k][n4+0] = split_tf32(v.x);
        Bs[k][n4+1] = split_tf32(v.y);
        Bs[k][n4+2] = split_tf32(v.z);
        Bs[k][n4+3] = split_tf32(v.w);
    }
}
// B fill along k: src row-major [n][k] (ld) -> Bs[k][n]   (scores: B[k=dk][n=s] = K[s][dk])
__device__ __forceinline__ void fillB_k(const float* __restrict__ src, int ld, int k0, int n0,
                                        float2 (*Bs)[PAD], int tid) {
    #pragma unroll
    for (int it = 0; it < 2; it++) {
        int idx = it*256 + tid;
        int n = idx >> 2, k4 = (idx & 3) << 2;
        float4 v = *(const float4*)(src + (size_t)(n0+n)*ld + k0 + k4);
        Bs[k4+0][n] = split_tf32(v.x);
        Bs[k4+1][n] = split_tf32(v.y);
        Bs[k4+2][n] = split_tf32(v.z);
        Bs[k4+3][n] = split_tf32(v.w);
    }
}

// one 16-deep k stage of warp mma: c[2 mtiles][8 ntiles][4]
__device__ __forceinline__ void warp_mma_stage(const float2 (*As)[PAD], const float2 (*Bs)[PAD],
                                               int mrow, int ncol, int kq, float c[2][8][4]) {
    #pragma unroll
    for (int k8o = 0; k8o < 16; k8o += 8) {
        uint32_t ah[2][4], al[2][4];
        #pragma unroll
        for (int mt = 0; mt < 2; mt++) {
            float2 x0 = As[k8o+kq  ][mrow + mt*16];
            float2 x1 = As[k8o+kq  ][mrow + mt*16 + 8];
            float2 x2 = As[k8o+4+kq][mrow + mt*16];
            float2 x3 = As[k8o+4+kq][mrow + mt*16 + 8];
            ah[mt][0] = __float_as_uint(x0.x); al[mt][0] = __float_as_uint(x0.y);
            ah[mt][1] = __float_as_uint(x1.x); al[mt][1] = __float_as_uint(x1.y);
            ah[mt][2] = __float_as_uint(x2.x); al[mt][2] = __float_as_uint(x2.y);
            ah[mt][3] = __float_as_uint(x3.x); al[mt][3] = __float_as_uint(x3.y);
        }
        #pragma unroll
        for (int nt = 0; nt < 8; nt++) {
            float2 y0 = Bs[k8o+kq  ][ncol + nt*8];
            float2 y1 = Bs[k8o+4+kq][ncol + nt*8];
            uint32_t bh0 = __float_as_uint(y0.x), bl0 = __float_as_uint(y0.y);
            uint32_t bh1 = __float_as_uint(y1.x), bl1 = __float_as_uint(y1.y);
            #pragma unroll
            for (int mt = 0; mt < 2; mt++) {
                mma8(c[mt][nt], ah[mt], bh0, bh1);
                mma8(c[mt][nt], ah[mt], bl0, bl1);
                mma8(c[mt][nt], al[mt], bh0, bh1);
            }
        }
    }
}

// ---------------- K2: QKV projection (4096x1536x512) ----------------
__global__ __launch_bounds__(256) void mma_qkv(const float* __restrict__ A,
                                               const float* __restrict__ B,
                                               const float* __restrict__ bias) {
    __shared__ float2 As[16][PAD], Bs[16][PAD];
    int tid = threadIdx.x, lane = tid & 31, wid = tid >> 5;
    int wm = wid >> 1, wn = wid & 1;
    int m0 = blockIdx.y * 128, n0 = blockIdx.x * 128;
    int mrow = wm*32 + (lane>>2), ncol = wn*64 + (lane>>2), kq = lane & 3;
    float c[2][8][4] = {};
    for (int k0 = 0; k0 < DMODEL; k0 += 16) {
        fillA_plain(A, DMODEL, m0, k0, As, tid);
        fillB_n(B, 3*DMODEL, k0, n0, Bs, tid);
        __syncthreads();
        warp_mma_stage(As, Bs, mrow, ncol, kq, c);
        __syncthreads();
    }
    int reg = blockIdx.x >> 2;
    float* dst = (reg == 0) ? g_q : ((reg == 1) ? g_k : g_v);
    #pragma unroll
    for (int mt = 0; mt < 2; mt++) {
        int r0 = m0 + wm*32 + mt*16 + (lane>>2);
        #pragma unroll
        for (int nt = 0; nt < 8; nt++) {
            int gcol = n0 + wn*64 + nt*8 + 2*kq;
            float2 bv = *(const float2*)(bias + gcol);
            int col = gcol - reg*512;
            *(float2*)(dst + (size_t)r0*DMODEL + col) =
                make_float2(c[mt][nt][0] + bv.x, c[mt][nt][1] + bv.y);
            *(float2*)(dst + (size_t)(r0+8)*DMODEL + col) =
                make_float2(c[mt][nt][2] + bv.x, c[mt][nt][3] + bv.y);
        }
    }
}

// ---------------- K3: scores + per-64col softmax stats (windowed) ----------------
__global__ __launch_bounds__(256) void mma_scores(const unsigned char* __restrict__ kpm) {
    __shared__ float2 As[16][PAD], Bs[16][PAD];
    int z = blockIdx.z; int h = z >> 2; int b = z & 3;
    int lo = g_dlo[h] & ~15;
    int hi = (g_dhi[h] + 15) & ~15;
    const float* Q  = g_q + (size_t)b*TT*DMODEL;
    const float* Kp = g_k + (size_t)b*TT*DMODEL;
    const float* m2 = g_m2 + h*DMODEL;
    int tid = threadIdx.x, lane = tid & 31, wid = tid >> 5;
    int wm = wid >> 1, wn = wid & 1;
    int t0 = blockIdx.y * 128, s0 = blockIdx.x * 128;
    int mrow = wm*32 + (lane>>2), ncol = wn*64 + (lane>>2), kq = lane & 3;
    float c[2][8][4] = {};
    for (int k0 = lo; k0 < hi; k0 += 16) {
        fillA_scaled(Q, DMODEL, t0, k0, m2, As, tid);
        fillB_k(Kp, DMODEL, k0, s0, Bs, tid);
        __syncthreads();
        warp_mma_stage(As, Bs, mrow, ncol, kq, c);
        __syncthreads();
    }
    float isc = g_inv_scale[h];
    float* Sout = g_scores + (size_t)z*TT*TT;
    // column padding mask (same for all rows)
    float km0[8], km1[8];
    #pragma unroll
    for (int nt = 0; nt < 8; nt++) {
        int sc = s0 + wn*64 + nt*8 + 2*kq;
        km0[nt] = kpm[b*TT + sc]     ? 1.0f : 0.0f;
        km1[nt] = kpm[b*TT + sc + 1] ? 1.0f : 0.0f;
    }
    int stile = blockIdx.x*2 + wn;
    #pragma unroll
    for (int mt = 0; mt < 2; mt++) {
        #pragma unroll
        for (int half = 0; half < 2; half++) {
            int t = t0 + wm*32 + mt*16 + (lane>>2) + half*8;
            float vv0[8], vv1[8];
            float mr = -INFINITY;
            #pragma unroll
            for (int nt = 0; nt < 8; nt++) {
                float x0 = c[mt][nt][half*2+0] * isc;
                float x1 = c[mt][nt][half*2+1] * isc;
                x0 = (km0[nt] != 0.0f) ? NEG_INF_F : x0;
                x1 = (km1[nt] != 0.0f) ? NEG_INF_F : x1;
                vv0[nt] = x0; vv1[nt] = x1;
                mr = fmaxf(mr, fmaxf(x0, x1));
            }
            mr = fmaxf(mr, __shfl_xor_sync(0xffffffffu, mr, 1));
            mr = fmaxf(mr, __shfl_xor_sync(0xffffffffu, mr, 2));
            float l = 0.0f;
            #pragma unroll
            for (int nt = 0; nt < 8; nt++)
                l += __expf(vv0[nt] - mr) + __expf(vv1[nt] - mr);
            l += __shfl_xor_sync(0xffffffffu, l, 1);
            l += __shfl_xor_sync(0xffffffffu, l, 2);
            if (kq == 0) {
                size_t ridx = ((size_t)z*TT + t)*NSTAT + stile;
                g_smax[ridx] = mr;
                g_ssum[ridx] = l;
            }
            #pragma unroll
            for (int nt = 0; nt < 8; nt++) {
                int sc = s0 + wn*64 + nt*8 + 2*kq;
                *(float2*)(Sout + (size_t)t*TT + sc) = make_float2(vv0[nt], vv1[nt]);
            }
        }
    }
}

// ---------------- K4: combine per-tile stats -> (m, 1/l) per row ----------------
__global__ __launch_bounds__(256) void combine_kernel() {
    int r = blockIdx.x * 256 + threadIdx.x;
    if (r >= NROWS) return;
    float mm = -INFINITY;
    float m[NSTAT], l[NSTAT];
    #pragma unroll
    for (int k = 0; k < NSTAT; k++) {
        m[k] = g_smax[(size_t)r*NSTAT + k];
        l[k] = g_ssum[(size_t)r*NSTAT + k];
        mm = fmaxf(mm, m[k]);
    }
    float ll = 0.0f;
    #pragma unroll
    for (int k = 0; k < NSTAT; k++) ll += l[k] * __expf(m[k] - mm);
    g_mrow[r] = mm;
    g_linv[r] = 1.0f / ll;
}

// ---------------- K5a: zero ctx ----------------
__global__ void zero_ctx_kernel() {
    int i = blockIdx.x * blockDim.x + threadIdx.x;
    ((float4*)g_ctx)[i] = make_float4(0.f, 0.f, 0.f, 0.f);
}

// ---------------- K5: ctx += softmax(S) @ (v*mask) (windowed d, atomic accumulate) ----------------
__global__ __launch_bounds__(256) void mma_ctx() {
    __shared__ float2 As[16][PAD], Bs[16][PAD];
    int z = blockIdx.z; int h = z >> 2; int b = z & 3;
    int dlo = g_dlo[h], dhi = g_dhi[h];
    int d0 = blockIdx.x * 128;
    if (d0 >= dhi || d0 + 128 <= dlo) return;
    const float* S   = g_scores + (size_t)z*TT*TT;
    const float* V   = g_v + (size_t)b*TT*DMODEL;
    const float* msk = g_maskv + h*DMODEL;
    int tid = threadIdx.x, lane = tid & 31, wid = tid >> 5;
    int wm = wid >> 1, wn = wid & 1;
    int t0 = blockIdx.y * 128;
    int zrow = z*TT + t0;
    int mrow = wm*32 + (lane>>2), ncol = wn*64 + (lane>>2), kq = lane & 3;
    float c[2][8][4] = {};
    for (int k0 = 0; k0 < TT; k0 += 16) {
        // A = P tile: exp(S - m) * linv, split to tf32 hi/lo
        #pragma unroll
        for (int it = 0; it < 2; it++) {
            int idx = it*256 + tid;
            int m = idx >> 2, k4 = (idx & 3) << 2;
            float mr = g_mrow[zrow + m];
            float li = g_linv[zrow + m];
            float4 v = *(const float4*)(S + (size_t)(t0+m)*TT + k0 + k4);
            As[k4+0][m] = split_tf32(__expf(v.x - mr) * li);
            As[k4+1][m] = split_tf32(__expf(v.y - mr) * li);
            As[k4+2][m] = split_tf32(__expf(v.z - mr) * li);
            As[k4+3][m] = split_tf32(__expf(v.w - mr) * li);
        }
        fillB_n(V, DMODEL, k0, d0, Bs, tid);
        __syncthreads();
        warp_mma_stage(As, Bs, mrow, ncol, kq, c);
        __syncthreads();
    }
    #pragma unroll
    for (int nt = 0; nt < 8; nt++) {
        int d = d0 + wn*64 + nt*8 + 2*kq;
        float mk0 = msk[d], mk1 = msk[d+1];
        bool in0 = (d >= dlo) && (d < dhi);
        bool in1 = (d+1 >= dlo) && (d+1 < dhi);
        #pragma unroll
        for (int mt = 0; mt < 2; mt++) {
            int r0 = t0 + wm*32 + mt*16 + (lane>>2);
            float* base0 = &g_ctx[(size_t)b*TT*DMODEL + (size_t)r0*DMODEL + d];
            float* base1 = base0 + 8*DMODEL;
            if (in0) {
                atomicAdd(base0,     c[mt][nt][0] * mk0);
                atomicAdd(base1,     c[mt][nt][2] * mk0);
            }
            if (in1) {
                atomicAdd(base0 + 1, c[mt][nt][1] * mk1);
                atomicAdd(base1 + 1, c[mt][nt][3] * mk1);
            }
        }
    }
}

// ---------------- K6: out = ctx @ Wout + bout + query ----------------
__global__ __launch_bounds__(256) void mma_out(const float* __restrict__ B,
                                               const float* __restrict__ bias,
                                               const float* __restrict__ resid) {
    __shared__ float2 As[16][PAD], Bs[16][PAD];
    int tid = threadIdx.x, lane = tid & 31, wid = tid >> 5;
    int wm = wid >> 1, wn = wid & 1;
    int m0 = blockIdx.y * 128, n0 = blockIdx.x * 128;
    int mrow = wm*32 + (lane>>2), ncol = wn*64 + (lane>>2), kq = lane & 3;
    float c[2][8][4] = {};
    for (int k0 = 0; k0 < DMODEL; k0 += 16) {
        fillA_plain(g_ctx, DMODEL, m0, k0, As, tid);
        fillB_n(B, DMODEL, k0, n0, Bs, tid);
        __syncthreads();
        warp_mma_stage(As, Bs, mrow, ncol, kq, c);
        __syncthreads();
    }
    #pragma unroll
    for (int mt = 0; mt < 2; mt++) {
        int r0 = m0 + wm*32 + mt*16 + (lane>>2);
        #pragma unroll
        for (int nt = 0; nt < 8; nt++) {
            int col = n0 + wn*64 + nt*8 + 2*kq;
            float2 bv = *(const float2*)(bias + col);
            float2 q0 = *(const float2*)(resid + (size_t)r0*DMODEL + col);
            float2 q1 = *(const float2*)(resid + (size_t)(r0+8)*DMODEL + col);
            *(float2*)(g_res + (size_t)r0*DMODEL + col) =
                make_float2(c[mt][nt][0] + bv.x + q0.x, c[mt][nt][1] + bv.y + q0.y);
            *(float2*)(g_res + (size_t)(r0+8)*DMODEL + col) =
                make_float2(c[mt][nt][2] + bv.x + q1.x, c[mt][nt][3] + bv.y + q1.y);
        }
    }
}

// ---------------- block reduce (LN) ----------------
__device__ __forceinline__ float block_reduce_sum(float v) {
    __shared__ float sh[32];
    __syncthreads();
    int lane = threadIdx.x & 31, wid = threadIdx.x >> 5;
    #pragma unroll
    for (int o = 16; o > 0; o >>= 1) v += __shfl_xor_sync(0xffffffffu, v, o);
    if (lane == 0) sh[wid] = v;
    __syncthreads();
    if (wid == 0) {
        int nw = blockDim.x >> 5;
        v = (lane < nw) ? sh[lane] : 0.0f;
        #pragma unroll
        for (int o = 16; o > 0; o >>= 1) v += __shfl_xor_sync(0xffffffffu, v, o);
        if (lane == 0) sh[0] = v;
    }
    __syncthreads();
    return sh[0];
}

// ---------------- K1: head params / masks / windows ----------------
__global__ void head_params_kernel(const float* __restrict__ hw) {
    __shared__ float dims[HH], starts[HH];
    int tid = threadIdx.x;
    if (tid == 0) {
        float mx = -1e30f;
        for (int h = 0; h < HH; h++) mx = fmaxf(mx, hw[h]);
        float e[HH]; float s = 0.0f;
        for (int h = 0; h < HH; h++) { e[h] = expf(hw[h] - mx); s += e[h]; }
        float run = 0.0f;
        const float adj = (float)(DMODEL - 16*HH);   // 384
        for (int h = 0; h < HH; h++) {
            float gg = e[h] / s;
            float dd = fmaxf(16.0f + gg * adj, 0.0f);
            dims[h] = dd; starts[h] = run;
            g_inv_scale[h] = rsqrtf(dd + 1e-6f);
            int lo = (int)floorf(run - 2.5f);        if (lo < 0) lo = 0;
            int hi = (int)ceilf(run + dd + 2.5f);    if (hi > DMODEL) hi = DMODEL;
            g_dlo[h] = lo; g_dhi[h] = hi;
            run += dd;
        }
    }
    __syncthreads();
    float p = (float)tid;   // tid in [0,512)
    for (int h = 0; h < HH; h++) {
        float l = 1.0f / (1.0f + expf(-(p - starts[h]) * 10.0f));
        float r = 1.0f / (1.0f + expf(-(starts[h] + dims[h] - p) * 10.0f));
        float m = l * r;
        g_maskv[h*DMODEL + tid] = m;
        g_m2[h*DMODEL + tid]   = m * m;
    }
}

// ---------------- K7: LayerNorm -> d_out ----------------
__global__ __launch_bounds__(256) void ln_kernel(const float* __restrict__ gamma,
                                                 const float* __restrict__ beta,
                                                 float* __restrict__ out) {
    int row = blockIdx.x;
    int tid = threadIdx.x;
    float2 v = ((const float2*)(g_res + (size_t)row*DMODEL))[tid];
    float s = block_reduce_sum(v.x + v.y);
    float mu = s * (1.0f / DMODEL);
    float d0 = v.x - mu, d1 = v.y - mu;
    float sq = block_reduce_sum(d0*d0 + d1*d1);
    float var = sq * (1.0f / DMODEL);
    float r = rsqrtf(var + 1e-5f);
    float2 g  = ((const float2*)gamma)[tid];
    float2 bt = ((const float2*)beta)[tid];
    float2 o;
    o.x = d0 * r * g.x + bt.x;
    o.y = d1 * r * g.y + bt.y;
    ((float2*)(out + (size_t)row*DMODEL))[tid] = o;
}

// ---------------- launch ----------------
extern "C" void kernel_launch(void* const* d_in, const int* in_sizes, int n_in,
                              void* d_out, int out_size) {
    const float* query = (const float*)d_in[0];
    const float* hw    = (const float*)d_in[1];
    const float* Wqkv  = (const float*)d_in[2];
    const float* bqkv  = (const float*)d_in[3];
    const float* Wout  = (const float*)d_in[4];
    const float* bout  = (const float*)d_in[5];
    const float* gamma = (const float*)d_in[6];
    const float* beta  = (const float*)d_in[7];
    const unsigned char* kpm = (const unsigned char*)d_in[8];
    float* out = (float*)d_out;

    head_params_kernel<<<1, DMODEL>>>(hw);
    mma_qkv<<<dim3(3*DMODEL/128, BB*TT/128), 256>>>(query, Wqkv, bqkv);
    zero_ctx_kernel<<<(BB*TT*DMODEL/4)/256, 256>>>();
    mma_scores<<<dim3(TT/128, TT/128, HH*BB), 256>>>(kpm);
    combine_kernel<<<NROWS/256, 256>>>();
    mma_ctx<<<dim3(DMODEL/128, TT/128, HH*BB), 256>>>();
    mma_out<<<dim3(DMODEL/128, BB*TT/128), 256>>>(Wout, bout, query);
    ln_kernel<<<BB*TT, 256>>>(gamma, beta, out);
}

// round 10
// speedup vs baseline: 1.1889x; 1.1889x over previous
#include <cuda_runtime.h>
#include <cstdint>
#include <math.h>

#define BB 4
#define TT 1024
#define DMODEL 512
#define HH 8
#define NEG_INF_F (-1000000000.0f)
#define NROWS (HH*BB*TT)   // 32768 softmax rows
#define NSTAT 16           // per-row stat slots (64-col granularity)

// ---------------- scratch (device globals; no allocation) ----------------
__device__ float g_q[BB*TT*DMODEL];
__device__ float g_k[BB*TT*DMODEL];
__device__ float g_v[BB*TT*DMODEL];
__device__ float g_res[BB*TT*DMODEL];
__device__ float g_scores[(size_t)HH*BB*TT*TT];   // stores exp(S - m_tile)
__device__ float g_smax[(size_t)NROWS*NSTAT];
__device__ float g_ssum[(size_t)NROWS*NSTAT];
__device__ float g_mrow[NROWS];
__device__ float g_linv[NROWS];
__device__ float g_maskv[HH*DMODEL];
__device__ float g_m2[HH*DMODEL];
__device__ float g_inv_scale[HH];
__device__ int   g_dlo[HH];
__device__ int   g_dhi[HH];
__device__ float g_ctx[BB*TT*DMODEL];

// ================= mma.sync tf32 machinery =================
__device__ __forceinline__ float tf32_rna(float x) {
    float r; asm("cvt.rna.tf32.f32 %0, %1;" : "=f"(r) : "f"(x)); return r;
}
// hi = rna(x); lo = x - hi (HW truncates operand bits to tf32 -> error ~2^-22)
__device__ __forceinline__ float2 split_tf32(float x) {
    float h = tf32_rna(x);
    return make_float2(h, x - h);
}
__device__ __forceinline__ void mma8(float c[4], const uint32_t a[4], uint32_t b0, uint32_t b1) {
    asm volatile(
        "mma.sync.aligned.m16n8k8.row.col.f32.tf32.tf32.f32 "
        "{%0,%1,%2,%3}, {%4,%5,%6,%7}, {%8,%9}, {%0,%1,%2,%3};"
        : "+f"(c[0]), "+f"(c[1]), "+f"(c[2]), "+f"(c[3])
        : "r"(a[0]), "r"(a[1]), "r"(a[2]), "r"(a[3]), "r"(b0), "r"(b1));
}

#define PAD 133    // float2 per k-row (A/B split tiles)
#define PADH 136   // float per k-row (hi-only P tile), 8k+m -> conflict-free

// A fill: src row-major [m][k] (ld) -> As[k][m] split
__device__ __forceinline__ void fillA_plain(const float* __restrict__ src, int ld, int m0, int k0,
                                            float2 (*As)[PAD], int tid) {
    #pragma unroll
    for (int it = 0; it < 2; it++) {
        int idx = it*256 + tid;
        int m = idx >> 2, k4 = (idx & 3) << 2;
        float4 v = *(const float4*)(src + (size_t)(m0+m)*ld + k0 + k4);
        As[k4+0][m] = split_tf32(v.x);
        As[k4+1][m] = split_tf32(v.y);
        As[k4+2][m] = split_tf32(v.z);
        As[k4+3][m] = split_tf32(v.w);
    }
}
// A fill with per-k scale (Q * m2) for scores
__device__ __forceinline__ void fillA_scaled(const float* __restrict__ src, int ld, int m0, int k0,
                                             const float* __restrict__ scl,
                                             float2 (*As)[PAD], int tid) {
    #pragma unroll
    for (int it = 0; it < 2; it++) {
        int idx = it*256 + tid;
        int m = idx >> 2, k4 = (idx & 3) << 2;
        float4 v = *(const float4*)(src + (size_t)(m0+m)*ld + k0 + k4);
        float4 s = *(const float4*)(scl + k0 + k4);
        As[k4+0][m] = split_tf32(v.x * s.x);
        As[k4+1][m] = split_tf32(v.y * s.y);
        As[k4+2][m] = split_tf32(v.z * s.z);
        As[k4+3][m] = split_tf32(v.w * s.w);
    }
}
// B fill along n: src row-major [k][n] (ld) -> Bs[k][n]
__device__ __forceinline__ void fillB_n(const float* __restrict__ src, int ld, int k0, int n0,
                                        float2 (*Bs)[PAD], int tid) {
    #pragma unroll
    for (int it = 0; it < 2; it++) {
        int idx = it*256 + tid;
        int k = idx >> 5, n4 = (idx & 31) << 2;
        float4 v = *(const float4*)(src + (size_t)(k0+k)*ld + n0 + n4);
        Bs[k][n4+0] = split_tf32(v.x);
        Bs[k][n4+1] = split_tf32(v.y);
        Bs[k][n4+2] = split_tf32(v.z);
        Bs[k][n4+3] = split_tf32(v.w);
    }
}
// B fill along k: src row-major [n][k] (ld) -> Bs[k][n]
__device__ __forceinline__ void fillB_k(const float* __restrict__ src, int ld, int k0, int n0,
                                        float2 (*Bs)[PAD], int tid) {
    #pragma unroll
    for (int it = 0; it < 2; it++) {
        int idx = it*256 + tid;
        int n = idx >> 2, k4 = (idx & 3) << 2;
        float4 v = *(const float4*)(src + (size_t)(n0+n)*ld + k0 + k4);
        Bs[k4+0][n] = split_tf32(v.x);
        Bs[k4+1][n] = split_tf32(v.y);
        Bs[k4+2][n] = split_tf32(v.z);
        Bs[k4+3][n] = split_tf32(v.w);
    }
}

// 3-term stage (qkv/scores/out)
__device__ __forceinline__ void warp_mma_stage(const float2 (*As)[PAD], const float2 (*Bs)[PAD],
                                               int mrow, int ncol, int kq, float c[2][8][4]) {
    #pragma unroll
    for (int k8o = 0; k8o < 16; k8o += 8) {
        uint32_t ah[2][4], al[2][4];
        #pragma unroll
        for (int mt = 0; mt < 2; mt++) {
            float2 x0 = As[k8o+kq  ][mrow + mt*16];
            float2 x1 = As[k8o+kq  ][mrow + mt*16 + 8];
            float2 x2 = As[k8o+4+kq][mrow + mt*16];
            float2 x3 = As[k8o+4+kq][mrow + mt*16 + 8];
            ah[mt][0] = __float_as_uint(x0.x); al[mt][0] = __float_as_uint(x0.y);
            ah[mt][1] = __float_as_uint(x1.x); al[mt][1] = __float_as_uint(x1.y);
            ah[mt][2] = __float_as_uint(x2.x); al[mt][2] = __float_as_uint(x2.y);
            ah[mt][3] = __float_as_uint(x3.x); al[mt][3] = __float_as_uint(x3.y);
        }
        #pragma unroll
        for (int nt = 0; nt < 8; nt++) {
            float2 y0 = Bs[k8o+kq  ][ncol + nt*8];
            float2 y1 = Bs[k8o+4+kq][ncol + nt*8];
            uint32_t bh0 = __float_as_uint(y0.x), bl0 = __float_as_uint(y0.y);
            uint32_t bh1 = __float_as_uint(y1.x), bl1 = __float_as_uint(y1.y);
            #pragma unroll
            for (int mt = 0; mt < 2; mt++) {
                mma8(c[mt][nt], ah[mt], bh0, bh1);
                mma8(c[mt][nt], ah[mt], bl0, bl1);
                mma8(c[mt][nt], al[mt], bh0, bh1);
            }
        }
    }
}

// 2-term PV stage (A = P hi-only, B = V split)
__device__ __forceinline__ void warp_mma_stage_pv(const float (*Ah)[PADH], const float2 (*Bs)[PAD],
                                                  int mrow, int ncol, int kq, float c[2][8][4]) {
    #pragma unroll
    for (int k8o = 0; k8o < 16; k8o += 8) {
        uint32_t ah[2][4];
        #pragma unroll
        for (int mt = 0; mt < 2; mt++) {
            ah[mt][0] = __float_as_uint(Ah[k8o+kq  ][mrow + mt*16]);
            ah[mt][1] = __float_as_uint(Ah[k8o+kq  ][mrow + mt*16 + 8]);
            ah[mt][2] = __float_as_uint(Ah[k8o+4+kq][mrow + mt*16]);
            ah[mt][3] = __float_as_uint(Ah[k8o+4+kq][mrow + mt*16 + 8]);
        }
        #pragma unroll
        for (int nt = 0; nt < 8; nt++) {
            float2 y0 = Bs[k8o+kq  ][ncol + nt*8];
            float2 y1 = Bs[k8o+4+kq][ncol + nt*8];
            uint32_t bh0 = __float_as_uint(y0.x), bl0 = __float_as_uint(y0.y);
            uint32_t bh1 = __float_as_uint(y1.x), bl1 = __float_as_uint(y1.y);
            #pragma unroll
            for (int mt = 0; mt < 2; mt++) {
                mma8(c[mt][nt], ah[mt], bh0, bh1);
                mma8(c[mt][nt], ah[mt], bl0, bl1);
            }
        }
    }
}

// ---------------- K2: QKV projection (4096x1536x512) ----------------
__global__ __launch_bounds__(256) void mma_qkv(const float* __restrict__ A,
                                               const float* __restrict__ B,
                                               const float* __restrict__ bias) {
    __shared__ float2 As[16][PAD], Bs[16][PAD];
    int tid = threadIdx.x, lane = tid & 31, wid = tid >> 5;
    int wm = wid >> 1, wn = wid & 1;
    int m0 = blockIdx.y * 128, n0 = blockIdx.x * 128;
    int mrow = wm*32 + (lane>>2), ncol = wn*64 + (lane>>2), kq = lane & 3;
    float c[2][8][4] = {};
    for (int k0 = 0; k0 < DMODEL; k0 += 16) {
        fillA_plain(A, DMODEL, m0, k0, As, tid);
        fillB_n(B, 3*DMODEL, k0, n0, Bs, tid);
        __syncthreads();
        warp_mma_stage(As, Bs, mrow, ncol, kq, c);
        __syncthreads();
    }
    int reg = blockIdx.x >> 2;
    float* dst = (reg == 0) ? g_q : ((reg == 1) ? g_k : g_v);
    #pragma unroll
    for (int mt = 0; mt < 2; mt++) {
        int r0 = m0 + wm*32 + mt*16 + (lane>>2);
        #pragma unroll
        for (int nt = 0; nt < 8; nt++) {
            int gcol = n0 + wn*64 + nt*8 + 2*kq;
            float2 bv = *(const float2*)(bias + gcol);
            int col = gcol - reg*512;
            *(float2*)(dst + (size_t)r0*DMODEL + col) =
                make_float2(c[mt][nt][0] + bv.x, c[mt][nt][1] + bv.y);
            *(float2*)(dst + (size_t)(r0+8)*DMODEL + col) =
                make_float2(c[mt][nt][2] + bv.x, c[mt][nt][3] + bv.y);
        }
    }
}

// ---------------- K3: scores -> exp(S - m_tile), stats per 64-col tile ----------------
__global__ __launch_bounds__(256) void mma_scores(const unsigned char* __restrict__ kpm) {
    __shared__ float2 As[16][PAD], Bs[16][PAD];
    int z = blockIdx.z; int h = z >> 2; int b = z & 3;
    int lo = g_dlo[h] & ~15;
    int hi = (g_dhi[h] + 15) & ~15;
    const float* Q  = g_q + (size_t)b*TT*DMODEL;
    const float* Kp = g_k + (size_t)b*TT*DMODEL;
    const float* m2 = g_m2 + h*DMODEL;
    int tid = threadIdx.x, lane = tid & 31, wid = tid >> 5;
    int wm = wid >> 1, wn = wid & 1;
    int t0 = blockIdx.y * 128, s0 = blockIdx.x * 128;
    int mrow = wm*32 + (lane>>2), ncol = wn*64 + (lane>>2), kq = lane & 3;
    float c[2][8][4] = {};
    for (int k0 = lo; k0 < hi; k0 += 16) {
        fillA_scaled(Q, DMODEL, t0, k0, m2, As, tid);
        fillB_k(Kp, DMODEL, k0, s0, Bs, tid);
        __syncthreads();
        warp_mma_stage(As, Bs, mrow, ncol, kq, c);
        __syncthreads();
    }
    float isc = g_inv_scale[h];
    float* Sout = g_scores + (size_t)z*TT*TT;
    float km0[8], km1[8];
    #pragma unroll
    for (int nt = 0; nt < 8; nt++) {
        int sc = s0 + wn*64 + nt*8 + 2*kq;
        km0[nt] = kpm[b*TT + sc]     ? 1.0f : 0.0f;
        km1[nt] = kpm[b*TT + sc + 1] ? 1.0f : 0.0f;
    }
    int stile = blockIdx.x*2 + wn;
    #pragma unroll
    for (int mt = 0; mt < 2; mt++) {
        #pragma unroll
        for (int half = 0; half < 2; half++) {
            int t = t0 + wm*32 + mt*16 + (lane>>2) + half*8;
            float vv0[8], vv1[8];
            float mr = -INFINITY;
            #pragma unroll
            for (int nt = 0; nt < 8; nt++) {
                float x0 = c[mt][nt][half*2+0] * isc;
                float x1 = c[mt][nt][half*2+1] * isc;
                x0 = (km0[nt] != 0.0f) ? NEG_INF_F : x0;
                x1 = (km1[nt] != 0.0f) ? NEG_INF_F : x1;
                vv0[nt] = x0; vv1[nt] = x1;
                mr = fmaxf(mr, fmaxf(x0, x1));
            }
            mr = fmaxf(mr, __shfl_xor_sync(0xffffffffu, mr, 1));
            mr = fmaxf(mr, __shfl_xor_sync(0xffffffffu, mr, 2));
            float l = 0.0f;
            #pragma unroll
            for (int nt = 0; nt < 8; nt++) {
                float e0 = __expf(vv0[nt] - mr);
                float e1 = __expf(vv1[nt] - mr);
                vv0[nt] = e0; vv1[nt] = e1;
                l += e0 + e1;
            }
            l += __shfl_xor_sync(0xffffffffu, l, 1);
            l += __shfl_xor_sync(0xffffffffu, l, 2);
            if (kq == 0) {
                size_t ridx = ((size_t)z*TT + t)*NSTAT + stile;
                g_smax[ridx] = mr;
                g_ssum[ridx] = l;
            }
            #pragma unroll
            for (int nt = 0; nt < 8; nt++) {
                int sc = s0 + wn*64 + nt*8 + 2*kq;
                *(float2*)(Sout + (size_t)t*TT + sc) = make_float2(vv0[nt], vv1[nt]);
            }
        }
    }
}

// ---------------- K4: combine per-tile stats -> (m, 1/l) per row ----------------
__global__ __launch_bounds__(256) void combine_kernel() {
    int r = blockIdx.x * 256 + threadIdx.x;
    if (r >= NROWS) return;
    float mm = -INFINITY;
    float m[NSTAT], l[NSTAT];
    #pragma unroll
    for (int k = 0; k < NSTAT; k++) {
        m[k] = g_smax[(size_t)r*NSTAT + k];
        l[k] = g_ssum[(size_t)r*NSTAT + k];
        mm = fmaxf(mm, m[k]);
    }
    float ll = 0.0f;
    #pragma unroll
    for (int k = 0; k < NSTAT; k++) ll += l[k] * __expf(m[k] - mm);
    g_mrow[r] = mm;
    g_linv[r] = 1.0f / ll;
}

// ---------------- K5a: zero ctx ----------------
__global__ void zero_ctx_kernel() {
    int i = blockIdx.x * blockDim.x + threadIdx.x;
    ((float4*)g_ctx)[i] = make_float4(0.f, 0.f, 0.f, 0.f);
}

// ---------------- K5: ctx += P @ (v*mask); P from stored exp * corr table ----------------
__global__ __launch_bounds__(256) void mma_ctx() {
    __shared__ float  Ah[16][PADH];
    __shared__ float2 Bs[16][PAD];
    __shared__ float  corr[128][NSTAT+1];
    int z = blockIdx.z; int h = z >> 2; int b = z & 3;
    int dlo = g_dlo[h], dhi = g_dhi[h];
    int d0 = blockIdx.x * 128;
    if (d0 >= dhi || d0 + 128 <= dlo) return;
    const float* S   = g_scores + (size_t)z*TT*TT;
    const float* V   = g_v + (size_t)b*TT*DMODEL;
    const float* msk = g_maskv + h*DMODEL;
    int tid = threadIdx.x, lane = tid & 31, wid = tid >> 5;
    int wm = wid >> 1, wn = wid & 1;
    int t0 = blockIdx.y * 128;
    int zrow = z*TT + t0;
    int mrow = wm*32 + (lane>>2), ncol = wn*64 + (lane>>2), kq = lane & 3;
    // build corr table: corr[row][tile] = exp(m_tile - m_row) * linv_row
    #pragma unroll
    for (int i = 0; i < 8; i++) {
        int idx = tid*8 + i;
        int row = idx >> 4, tile = idx & 15;
        float mr = g_mrow[zrow + row];
        float li = g_linv[zrow + row];
        float mt = g_smax[(size_t)(zrow + row)*NSTAT + tile];
        corr[row][tile] = __expf(mt - mr) * li;
    }
    __syncthreads();
    float c[2][8][4] = {};
    for (int k0 = 0; k0 < TT; k0 += 16) {
        #pragma unroll
        for (int it = 0; it < 2; it++) {
            int idx = it*256 + tid;
            int m = idx >> 2, k4 = (idx & 3) << 2;
            float cr = corr[m][(k0 + k4) >> 6];
            float4 v = *(const float4*)(S + (size_t)(t0+m)*TT + k0 + k4);
            Ah[k4+0][m] = tf32_rna(v.x * cr);
            Ah[k4+1][m] = tf32_rna(v.y * cr);
            Ah[k4+2][m] = tf32_rna(v.z * cr);
            Ah[k4+3][m] = tf32_rna(v.w * cr);
        }
        fillB_n(V, DMODEL, k0, d0, Bs, tid);
        __syncthreads();
        warp_mma_stage_pv(Ah, Bs, mrow, ncol, kq, c);
        __syncthreads();
    }
    #pragma unroll
    for (int nt = 0; nt < 8; nt++) {
        int d = d0 + wn*64 + nt*8 + 2*kq;
        float mk0 = msk[d], mk1 = msk[d+1];
        bool in0 = (d >= dlo) && (d < dhi);
        bool in1 = (d+1 >= dlo) && (d+1 < dhi);
        #pragma unroll
        for (int mt = 0; mt < 2; mt++) {
            int r0 = t0 + wm*32 + mt*16 + (lane>>2);
            float* base0 = &g_ctx[(size_t)b*TT*DMODEL + (size_t)r0*DMODEL + d];
            float* base1 = base0 + 8*DMODEL;
            if (in0) {
                atomicAdd(base0,     c[mt][nt][0] * mk0);
                atomicAdd(base1,     c[mt][nt][2] * mk0);
            }
            if (in1) {
                atomicAdd(base0 + 1, c[mt][nt][1] * mk1);
                atomicAdd(base1 + 1, c[mt][nt][3] * mk1);
            }
        }
    }
}

// ---------------- K6: out = ctx @ Wout + bout + query ----------------
__global__ __launch_bounds__(256) void mma_out(const float* __restrict__ B,
                                               const float* __restrict__ bias,
                                               const float* __restrict__ resid) {
    __shared__ float2 As[16][PAD], Bs[16][PAD];
    int tid = threadIdx.x, lane = tid & 31, wid = tid >> 5;
    int wm = wid >> 1, wn = wid & 1;
    int m0 = blockIdx.y * 128, n0 = blockIdx.x * 128;
    int mrow = wm*32 + (lane>>2), ncol = wn*64 + (lane>>2), kq = lane & 3;
    float c[2][8][4] = {};
    for (int k0 = 0; k0 < DMODEL; k0 += 16) {
        fillA_plain(g_ctx, DMODEL, m0, k0, As, tid);
        fillB_n(B, DMODEL, k0, n0, Bs, tid);
        __syncthreads();
        warp_mma_stage(As, Bs, mrow, ncol, kq, c);
        __syncthreads();
    }
    #pragma unroll
    for (int mt = 0; mt < 2; mt++) {
        int r0 = m0 + wm*32 + mt*16 + (lane>>2);
        #pragma unroll
        for (int nt = 0; nt < 8; nt++) {
            int col = n0 + wn*64 + nt*8 + 2*kq;
            float2 bv = *(const float2*)(bias + col);
            float2 q0 = *(const float2*)(resid + (size_t)r0*DMODEL + col);
            float2 q1 = *(const float2*)(resid + (size_t)(r0+8)*DMODEL + col);
            *(float2*)(g_res + (size_t)r0*DMODEL + col) =
                make_float2(c[mt][nt][0] + bv.x + q0.x, c[mt][nt][1] + bv.y + q0.y);
            *(float2*)(g_res + (size_t)(r0+8)*DMODEL + col) =
                make_float2(c[mt][nt][2] + bv.x + q1.x, c[mt][nt][3] + bv.y + q1.y);
        }
    }
}

// ---------------- block reduce (LN) ----------------
__device__ __forceinline__ float block_reduce_sum(float v) {
    __shared__ float sh[32];
    __syncthreads();
    int lane = threadIdx.x & 31, wid = threadIdx.x >> 5;
    #pragma unroll
    for (int o = 16; o > 0; o >>= 1) v += __shfl_xor_sync(0xffffffffu, v, o);
    if (lane == 0) sh[wid] = v;
    __syncthreads();
    if (wid == 0) {
        int nw = blockDim.x >> 5;
        v = (lane < nw) ? sh[lane] : 0.0f;
        #pragma unroll
        for (int o = 16; o > 0; o >>= 1) v += __shfl_xor_sync(0xffffffffu, v, o);
        if (lane == 0) sh[0] = v;
    }
    __syncthreads();
    return sh[0];
}

// ---------------- K1: head params / masks / windows ----------------
__global__ void head_params_kernel(const float* __restrict__ hw) {
    __shared__ float dims[HH], starts[HH];
    int tid = threadIdx.x;
    if (tid == 0) {
        float mx = -1e30f;
        for (int h = 0; h < HH; h++) mx = fmaxf(mx, hw[h]);
        float e[HH]; float s = 0.0f;
        for (int h = 0; h < HH; h++) { e[h] = expf(hw[h] - mx); s += e[h]; }
        float run = 0.0f;
        const float adj = (float)(DMODEL - 16*HH);   // 384
        for (int h = 0; h < HH; h++) {
            float gg = e[h] / s;
            float dd = fmaxf(16.0f + gg * adj, 0.0f);
            dims[h] = dd; starts[h] = run;
            g_inv_scale[h] = rsqrtf(dd + 1e-6f);
            int lo = (int)floorf(run - 2.5f);        if (lo < 0) lo = 0;
            int hi = (int)ceilf(run + dd + 2.5f);    if (hi > DMODEL) hi = DMODEL;
            g_dlo[h] = lo; g_dhi[h] = hi;
            run += dd;
        }
    }
    __syncthreads();
    float p = (float)tid;   // tid in [0,512)
    for (int h = 0; h < HH; h++) {
        float l = 1.0f / (1.0f + expf(-(p - starts[h]) * 10.0f));
        float r = 1.0f / (1.0f + expf(-(starts[h] + dims[h] - p) * 10.0f));
        float m = l * r;
        g_maskv[h*DMODEL + tid] = m;
        g_m2[h*DMODEL + tid]   = m * m;
    }
}

// ---------------- K7: LayerNorm -> d_out ----------------
__global__ __launch_bounds__(256) void ln_kernel(const float* __restrict__ gamma,
                                                 const float* __restrict__ beta,
                                                 float* __restrict__ out) {
    int row = blockIdx.x;
    int tid = threadIdx.x;
    float2 v = ((const float2*)(g_res + (size_t)row*DMODEL))[tid];
    float s = block_reduce_sum(v.x + v.y);
    float mu = s * (1.0f / DMODEL);
    float d0 = v.x - mu, d1 = v.y - mu;
    float sq = block_reduce_sum(d0*d0 + d1*d1);
    float var = sq * (1.0f / DMODEL);
    float r = rsqrtf(var + 1e-5f);
    float2 g  = ((const float2*)gamma)[tid];
    float2 bt = ((const float2*)beta)[tid];
    float2 o;
    o.x = d0 * r * g.x + bt.x;
    o.y = d1 * r * g.y + bt.y;
    ((float2*)(out + (size_t)row*DMODEL))[tid] = o;
}

// ---------------- launch ----------------
extern "C" void kernel_launch(void* const* d_in, const int* in_sizes, int n_in,
                              void* d_out, int out_size) {
    const float* query = (const float*)d_in[0];
    const float* hw    = (const float*)d_in[1];
    const float* Wqkv  = (const float*)d_in[2];
    const float* bqkv  = (const float*)d_in[3];
    const float* Wout  = (const float*)d_in[4];
    const float* bout  = (const float*)d_in[5];
    const float* gamma = (const float*)d_in[6];
    const float* beta  = (const float*)d_in[7];
    const unsigned char* kpm = (const unsigned char*)d_in[8];
    float* out = (float*)d_out;

    head_params_kernel<<<1, DMODEL>>>(hw);
    mma_qkv<<<dim3(3*DMODEL/128, BB*TT/128), 256>>>(query, Wqkv, bqkv);
    zero_ctx_kernel<<<(BB*TT*DMODEL/4)/256, 256>>>();
    mma_scores<<<dim3(TT/128, TT/128, HH*BB), 256>>>(kpm);
    combine_kernel<<<NROWS/256, 256>>>();
    mma_ctx<<<dim3(DMODEL/128, TT/128, HH*BB), 256>>>();
    mma_out<<<dim3(DMODEL/128, BB*TT/128), 256>>>(Wout, bout, query);
    ln_kernel<<<BB*TT, 256>>>(gamma, beta, out);
}